// round 1
// baseline (speedup 1.0000x reference)
#include <cuda_runtime.h>
#include <math.h>
#include <float.h>

#define BB 64
#define CC 100
#define KK 5
#define NN (BB*CC*KK)      // 32000
#define NBINS 4096

// ---------------- device scratch (no allocs allowed) ----------------
__device__ float g_t[NN], g_s[NN], g_d[NN];
__device__ float g_tk[KK*BB*CC], g_sk[KK*BB*CC];   // k-major copies for Gram kernels
__device__ float g_ds[NN], g_tso[NN], g_sso[NN];   // bin-sorted d, t, s
__device__ int   g_count[NBINS], g_off[NBINS+1], g_cur[NBINS];
__device__ float g_binT[NBINS], g_binS[NBINS];
__device__ float g_PT[NBINS+1], g_PS[NBINS+1];
__device__ unsigned g_dminU, g_dmaxU;
__device__ double g_tt, g_ss, g_ts;
__device__ double g_kl[KK], g_ce, g_l1, g_sub;

// ---------------- helpers ----------------
__device__ __forceinline__ unsigned f2mono(float f){
    unsigned u = __float_as_uint(f);
    return (u & 0x80000000u) ? ~u : (u | 0x80000000u);
}
__device__ __forceinline__ float mono2f(unsigned u){
    return (u & 0x80000000u) ? __uint_as_float(u ^ 0x80000000u)
                             : __uint_as_float(~u);
}
__device__ __forceinline__ int binOf(float x, float dmin, float invw){
    int j = (int)floorf((x - dmin) * invw);
    return min(max(j, 0), NBINS-1);
}

__device__ __forceinline__ float blockReduceSumAll(float v){
    __shared__ float sh[33];
    int lane = threadIdx.x & 31, w = threadIdx.x >> 5;
    #pragma unroll
    for (int o=16;o;o>>=1) v += __shfl_down_sync(0xffffffffu, v, o);
    if (lane==0) sh[w] = v;
    __syncthreads();
    if (threadIdx.x==0){
        float s = 0.f; int nw = (blockDim.x + 31) >> 5;
        for (int i=0;i<nw;i++) s += sh[i];
        sh[32] = s;
    }
    __syncthreads();
    float r = sh[32];
    __syncthreads();
    return r;
}
__device__ __forceinline__ float blockReduceMaxAll(float v){
    __shared__ float sh[33];
    int lane = threadIdx.x & 31, w = threadIdx.x >> 5;
    #pragma unroll
    for (int o=16;o;o>>=1) v = fmaxf(v, __shfl_down_sync(0xffffffffu, v, o));
    if (lane==0) sh[w] = v;
    __syncthreads();
    if (threadIdx.x==0){
        float s = -FLT_MAX; int nw = (blockDim.x + 31) >> 5;
        for (int i=0;i<nw;i++) s = fmaxf(s, sh[i]);
        sh[32] = s;
    }
    __syncthreads();
    float r = sh[32];
    __syncthreads();
    return r;
}
__device__ __forceinline__ float blockReduceMinAll(float v){
    __shared__ float sh[33];
    int lane = threadIdx.x & 31, w = threadIdx.x >> 5;
    #pragma unroll
    for (int o=16;o;o>>=1) v = fminf(v, __shfl_down_sync(0xffffffffu, v, o));
    if (lane==0) sh[w] = v;
    __syncthreads();
    if (threadIdx.x==0){
        float s = FLT_MAX; int nw = (blockDim.x + 31) >> 5;
        for (int i=0;i<nw;i++) s = fminf(s, sh[i]);
        sh[32] = s;
    }
    __syncthreads();
    float r = sh[32];
    __syncthreads();
    return r;
}

// ---------------- kernels ----------------
__global__ void k_init(){
    int i = threadIdx.x;
    for (int j=i; j<NBINS; j+=1024){
        g_count[j]=0; g_cur[j]=0; g_binT[j]=0.f; g_binS[j]=0.f;
    }
    if (i==0){
        g_dminU = 0xFFFFFFFFu; g_dmaxU = 0u;
        g_tt = g_ss = g_ts = 0.0;
        g_ce = 0.0; g_l1 = 0.0; g_sub = 0.0;
        for (int k=0;k<KK;k++) g_kl[k] = 0.0;
    }
}

// one block per (row b, temp k): softmaxes, d=log t-log s, KD pieces, L2 dots
__global__ void k_softmax(const float* __restrict__ lsg,
                          const float* __restrict__ ltg,
                          const int*   __restrict__ tgt){
    int b = blockIdx.x / KK;
    int k = blockIdx.x % KK;
    float invT = 1.0f / (float)(k+1);
    int tid = threadIdx.x;
    bool act = tid < CC;

    float a  = act ? lsg[b*CC + tid] * invT : -FLT_MAX;   // student / T
    float bt = act ? ltg[b*CC + tid] * invT : -FLT_MAX;   // teacher / T

    float amax = blockReduceMaxAll(a);
    float bmax = blockReduceMaxAll(bt);
    float ea = act ? expf(a  - amax) : 0.f;
    float eb = act ? expf(bt - bmax) : 0.f;
    float sumA = blockReduceSumAll(ea);
    float sumB = blockReduceSumAll(eb);
    float lA = logf(sumA), lB = logf(sumB);

    float sv=0.f, tv=0.f, dv=0.f, klp=0.f;
    if (act){
        float lq = a  - amax - lA;      // log softmax student
        float lp = bt - bmax - lB;      // log softmax teacher
        sv = ea / sumA;
        tv = eb / sumB;
        dv = lp - lq;
        klp = tv * dv;                  // p*(log p - log q)
        int idx = (b*CC + tid)*KK + k;  // matches reshape of [B,C,K]
        g_t[idx]=tv; g_s[idx]=sv; g_d[idx]=dv;
        int idx2 = (k*BB + b)*CC + tid;
        g_tk[idx2]=tv; g_sk[idx2]=sv;
        if (k==0 && tid == tgt[b]) atomicAdd(&g_ce, (double)(-lq));
    }
    float r;
    r = blockReduceSumAll(klp);   if (tid==0) atomicAdd(&g_kl[k], (double)r);
    r = blockReduceSumAll(tv*tv); if (tid==0) atomicAdd(&g_tt, (double)r);
    r = blockReduceSumAll(sv*sv); if (tid==0) atomicAdd(&g_ss, (double)r);
    r = blockReduceSumAll(tv*sv); if (tid==0) atomicAdd(&g_ts, (double)r);
    float mn = blockReduceMinAll(act ? dv :  FLT_MAX);
    float mx = blockReduceMaxAll(act ? dv : -FLT_MAX);
    if (tid==0){
        atomicMin(&g_dminU, f2mono(mn));
        atomicMax(&g_dmaxU, f2mono(mx));
    }
}

__global__ void k_hist(){
    int a = blockIdx.x*blockDim.x + threadIdx.x;
    if (a >= NN) return;
    float dmin = mono2f(g_dminU), dmax = mono2f(g_dmaxU);
    float invw = (float)NBINS / fmaxf(dmax - dmin, 1e-20f);
    int j = binOf(g_d[a], dmin, invw);
    atomicAdd(&g_count[j], 1);
    atomicAdd(&g_binT[j], g_t[a]);
    atomicAdd(&g_binS[j], g_s[a]);
}

// single-block exclusive scan over NBINS bins (counts, binT, binS)
__global__ void k_scan(){
    __shared__ int   sC[1024];
    __shared__ float sT[1024], sS[1024];
    int tid = threadIdx.x;
    int base = tid*4;
    int   c0=g_count[base],  c1=g_count[base+1],  c2=g_count[base+2],  c3=g_count[base+3];
    float t0=g_binT[base],   t1=g_binT[base+1],   t2=g_binT[base+2],   t3=g_binT[base+3];
    float s0=g_binS[base],   s1=g_binS[base+1],   s2=g_binS[base+2],   s3=g_binS[base+3];
    sC[tid]=c0+c1+c2+c3; sT[tid]=t0+t1+t2+t3; sS[tid]=s0+s1+s2+s3;
    __syncthreads();
    for (int off=1; off<1024; off<<=1){
        int vC = sC[tid]; float vT = sT[tid], vS = sS[tid];
        int uC=0; float uT=0.f, uS=0.f;
        if (tid >= off){ uC=sC[tid-off]; uT=sT[tid-off]; uS=sS[tid-off]; }
        __syncthreads();
        sC[tid]=vC+uC; sT[tid]=vT+uT; sS[tid]=vS+uS;
        __syncthreads();
    }
    int   exC = tid ? sC[tid-1] : 0;
    float exT = tid ? sT[tid-1] : 0.f;
    float exS = tid ? sS[tid-1] : 0.f;
    g_off[base  ]=exC; g_PT[base  ]=exT; g_PS[base  ]=exS; exC+=c0; exT+=t0; exS+=s0;
    g_off[base+1]=exC; g_PT[base+1]=exT; g_PS[base+1]=exS; exC+=c1; exT+=t1; exS+=s1;
    g_off[base+2]=exC; g_PT[base+2]=exT; g_PS[base+2]=exS; exC+=c2; exT+=t2; exS+=s2;
    g_off[base+3]=exC; g_PT[base+3]=exT; g_PS[base+3]=exS; exC+=c3; exT+=t3; exS+=s3;
    if (tid==1023){ g_off[NBINS]=exC; g_PT[NBINS]=exT; g_PS[NBINS]=exS; }
}

__global__ void k_scatter(){
    int a = blockIdx.x*blockDim.x + threadIdx.x;
    if (a >= NN) return;
    float dmin = mono2f(g_dminU), dmax = mono2f(g_dmaxU);
    float invw = (float)NBINS / fmaxf(dmax - dmin, 1e-20f);
    float dv = g_d[a];
    int j = binOf(dv, dmin, invw);
    int pos = g_off[j] + atomicAdd(&g_cur[j], 1);
    g_ds[pos]=dv; g_tso[pos]=g_t[a]; g_sso[pos]=g_s[a];
}

// L1 = sum_a [ t_a(2*P_t(a) - T) - s_a(2*P_s(a) - S) ],
// P_t(a) = sum of t_b over { b : d_b > -d_a }  (suffix of bins + exact boundary bin)
__global__ void k_main(){
    int a = blockIdx.x*blockDim.x + threadIdx.x;
    float contrib = 0.f;
    if (a < NN){
        float dmin = mono2f(g_dminU), dmax = mono2f(g_dmaxU);
        float invw = (float)NBINS / fmaxf(dmax - dmin, 1e-20f);
        float Ttot = g_PT[NBINS], Stot = g_PS[NBINS];
        float x = -g_d[a];
        int j = binOf(x, dmin, invw);
        float pt = Ttot - g_PT[j+1];   // bins strictly above j
        float ps = Stot - g_PS[j+1];
        int e0 = g_off[j], e1 = g_off[j+1];
        for (int m=e0; m<e1; ++m){
            if (g_ds[m] > x){ pt += g_tso[m]; ps += g_sso[m]; }
        }
        contrib = g_t[a]*(2.f*pt - Ttot) - g_s[a]*(2.f*ps - Stot);
    }
    float r = blockReduceSumAll(contrib);
    if (threadIdx.x==0) atomicAdd(&g_l1, (double)r);
}

// sub losses: G_k = T_k T_k^T - S_k S_k^T  (BxB), H_k = T_k^T T_k - S_k^T S_k (CxC)
__global__ void k_gram(){
    int e = blockIdx.x*blockDim.x + threadIdx.x;
    float val = 0.f;
    if (e < KK*BB*BB){
        int k = e / (BB*BB); int r = e - k*BB*BB; int i = r / BB; int j = r % BB;
        const float* Ti = g_tk + (k*BB+i)*CC;
        const float* Tj = g_tk + (k*BB+j)*CC;
        const float* Si = g_sk + (k*BB+i)*CC;
        const float* Sj = g_sk + (k*BB+j)*CC;
        float acc = 0.f;
        #pragma unroll 4
        for (int c=0;c<CC;c++) acc += Ti[c]*Tj[c] - Si[c]*Sj[c];
        val = acc*acc;
    } else if (e < KK*BB*BB + KK*CC*CC){
        int e2 = e - KK*BB*BB;
        int k = e2 / (CC*CC); int r = e2 - k*CC*CC; int i = r / CC; int j = r % CC;
        const float* Tk = g_tk + k*BB*CC;
        const float* Sk = g_sk + k*BB*CC;
        float acc = 0.f;
        #pragma unroll 4
        for (int b2=0;b2<BB;b2++)
            acc += Tk[b2*CC+i]*Tk[b2*CC+j] - Sk[b2*CC+i]*Sk[b2*CC+j];
        val = acc*acc;
    }
    float r2 = blockReduceSumAll(val);
    if (threadIdx.x==0) atomicAdd(&g_sub, (double)r2);
}

__global__ void k_final(float* __restrict__ out){
    double ce = g_ce / (double)BB;
    double kd = 0.0;
    for (int k=0;k<KK;k++){
        double temp = (double)(k+1);
        kd += (g_kl[k] / (double)(BB*CC)) * (0.7*temp*temp) + ce * 0.3;
    }
    double tt=g_tt, ss=g_ss, ts=g_ts;
    double l2 = 0.00025*(tt*tt - 2.0*ts*ts + ss*ss);
    double l1 = 0.00025*g_l1;
    out[0] = (float)(kd + l1 + l2 + g_sub);
}

// ---------------- launch ----------------
extern "C" void kernel_launch(void* const* d_in, const int* in_sizes, int n_in,
                              void* d_out, int out_size){
    (void)in_sizes; (void)n_in; (void)out_size;
    const float* ls  = (const float*)d_in[0];  // logits_student [64,100]
    const float* lt  = (const float*)d_in[1];  // logits_teacher [64,100]
    const int*   tgt = (const int*)  d_in[2];  // target [64]
    float* out = (float*)d_out;

    k_init    <<<1, 1024>>>();
    k_softmax <<<BB*KK, 128>>>(ls, lt, tgt);
    k_gram    <<<(KK*BB*BB + KK*CC*CC + 255)/256, 256>>>();
    k_hist    <<<(NN+255)/256, 256>>>();
    k_scan    <<<1, 1024>>>();
    k_scatter <<<(NN+255)/256, 256>>>();
    k_main    <<<(NN+255)/256, 256>>>();
    k_final   <<<1, 1>>>(out);
}